// round 1
// baseline (speedup 1.0000x reference)
#include <cuda_runtime.h>
#include <math.h>

// Problem constants
#define CI 16
#define CO 16
#define IN_H 256
#define IN_W 256
#define OUT_H 254
#define OUT_W 254

// Tiling: 256 threads; thread = (tx 0..15)*(ty 0..7)*(tz 0..1)
// thread computes 2 rows x 4 cols x 8 cout  (as f32x2 pairs)
#define TX 16
#define TY 8
#define TILE_W 64   // TX * 4
#define TILE_H 16   // TY * 2
#define SM_ROWS 18  // TILE_H + 2
#define SM_COLS 66  // TILE_W + 2
#define SM_STRIDE 68
#define CHUNK 4     // ci chunk held in smem

typedef unsigned long long u64;

__device__ __forceinline__ u64 pack2(float lo, float hi) {
    u64 r; asm("mov.b64 %0, {%1,%2};" : "=l"(r) : "f"(lo), "f"(hi)); return r;
}
__device__ __forceinline__ void unpack2(u64 v, float& lo, float& hi) {
    asm("mov.b64 {%0,%1}, %2;" : "=f"(lo), "=f"(hi) : "l"(v));
}
// packed fp32x2 FMA: d = a*b + d   (SASS FFMA2 on sm_103a)
__device__ __forceinline__ void fma2(u64& d, u64 a, u64 b) {
    asm("fma.rn.f32x2 %0, %1, %2, %0;" : "+l"(d) : "l"(a), "l"(b));
}

// mish(v) = v * tanh(softplus(v)) = v * ((1+e^v)^2 - 1) / ((1+e^v)^2 + 1)
__device__ __forceinline__ float mish_f(float v) {
    if (v > 30.0f) return v;          // avoid overflow of (1+e)^2; tanh==1 here
    float e  = __expf(v);
    float t  = 1.0f + e;
    float t2 = t * t;
    return v * __fdividef(t2 - 1.0f, t2 + 1.0f);
}

__global__ __launch_bounds__(256, 1)
void conv_mish_kernel(const float* __restrict__ x,
                      const float* __restrict__ w,
                      const float* __restrict__ bias,
                      float* __restrict__ y)
{
    __shared__ __align__(16) float xin[CHUNK * SM_ROWS * SM_STRIDE]; // 19584 B
    __shared__ __align__(16) float wsm[CI * 9 * CO * 2];             // 18432 B (dup pairs)
    __shared__ float bsm[CO];

    const int tid    = threadIdx.x;
    const int tile_x = blockIdx.x * TILE_W;
    const int tile_y = blockIdx.y * TILE_H;
    const int n      = blockIdx.z;

    // ---- preload weights as duplicated f32 pairs: wsm_pair[(ci*9+k)*CO + co] = (w,w)
    for (int i = tid; i < CO * CI * 9; i += 256) {
        int co  = i / (CI * 9);
        int rem = i - co * (CI * 9);       // ci*9 + k
        float wv = w[i];
        int p = (rem * CO + co) * 2;
        wsm[p] = wv; wsm[p + 1] = wv;
    }
    if (tid < CO) bsm[tid] = bias[tid];

    const int tx = tid & 15;
    const int ty = (tid >> 4) & 7;
    const int tz = tid >> 7;
    const int x0 = tx * 4;        // local out col base
    const int r0 = ty * 2;        // local out row base
    const int cobase = tz * 8;

    u64 acc[8][2][2];
    #pragma unroll
    for (int c = 0; c < 8; c++)
        #pragma unroll
        for (int r = 0; r < 2; r++)
            #pragma unroll
            for (int j = 0; j < 2; j++) acc[c][r][j] = 0ull;

    const float* xn = x + ((size_t)n * CI) * (IN_H * IN_W);

    for (int cc = 0; cc < CI / CHUNK; cc++) {
        if (cc) __syncthreads();   // previous chunk's compute done before overwrite
        // ---- load input chunk (coalesced, halo zero-filled)
        for (int i = tid; i < CHUNK * SM_ROWS * SM_COLS; i += 256) {
            int c   = i % SM_COLS;
            int t   = i / SM_COLS;
            int r   = t % SM_ROWS;
            int ci4 = t / SM_ROWS;
            int gy = tile_y + r;
            int gx = tile_x + c;
            float v = 0.0f;
            if (gy < IN_H && gx < IN_W)
                v = xn[((cc * CHUNK + ci4) * IN_H + gy) * IN_W + gx];
            xin[(ci4 * SM_ROWS + r) * SM_STRIDE + c] = v;
        }
        __syncthreads();

        #pragma unroll
        for (int ci4 = 0; ci4 < CHUNK; ci4++) {
            const float* xp = xin + ci4 * SM_ROWS * SM_STRIDE;
            const int ci = cc * CHUNK + ci4;
            #pragma unroll
            for (int ky = 0; ky < 3; ky++) {
                // weights for this (ci, ky): 3 kx * 8 cout dup-pairs, vectorized broadcast loads
                u64 wv[3][8];
                const ulonglong2* wp = (const ulonglong2*)
                    ((const u64*)wsm + ((ci * 9 + ky * 3) * CO + cobase));
                #pragma unroll
                for (int kx = 0; kx < 3; kx++) {
                    #pragma unroll
                    for (int c2 = 0; c2 < 4; c2++) {
                        ulonglong2 t = wp[kx * 8 + c2];   // kx advances by CO=16 u64 = 8 ull2
                        wv[kx][2 * c2]     = t.x;
                        wv[kx][2 * c2 + 1] = t.y;
                    }
                }
                // inputs: 2 rows, 6 cols each, via LDS.128 + LDS.64 (conflict-free)
                u64 P[2][5];
                #pragma unroll
                for (int r = 0; r < 2; r++) {
                    const float* ip = xp + (r0 + ky + r) * SM_STRIDE + x0;
                    float4 a  = *(const float4*)ip;
                    float2 b2 = *(const float2*)(ip + 4);
                    P[r][0] = pack2(a.x, a.y);
                    P[r][1] = pack2(a.y, a.z);
                    P[r][2] = pack2(a.z, a.w);
                    P[r][3] = pack2(a.w, b2.x);
                    P[r][4] = pack2(b2.x, b2.y);
                }
                // 96 packed FMAs
                #pragma unroll
                for (int kx = 0; kx < 3; kx++)
                    #pragma unroll
                    for (int c = 0; c < 8; c++)
                        #pragma unroll
                        for (int r = 0; r < 2; r++)
                            #pragma unroll
                            for (int j = 0; j < 2; j++)
                                fma2(acc[c][r][j], wv[kx][c], P[r][2 * j + kx]);
            }
        }
    }

    // ---- epilogue: +bias - 0.7, mish, store as float2 (pairs never straddle the 254 edge)
    #pragma unroll
    for (int c = 0; c < 8; c++) {
        int co = cobase + c;
        float badd = bsm[co] - 0.7f;
        #pragma unroll
        for (int r = 0; r < 2; r++) {
            int oy = tile_y + r0 + r;
            if (oy >= OUT_H) continue;
            float* yrow = y + (((size_t)n * CO + co) * OUT_H + oy) * OUT_W;
            #pragma unroll
            for (int j = 0; j < 2; j++) {
                int ox = tile_x + x0 + 2 * j;
                if (ox < OUT_W) {
                    float lo, hi; unpack2(acc[c][r][j], lo, hi);
                    float2 o;
                    o.x = mish_f(lo + badd);
                    o.y = mish_f(hi + badd);
                    *(float2*)(yrow + ox) = o;   // 8B-aligned: row base & ox both even
                }
            }
        }
    }
}

extern "C" void kernel_launch(void* const* d_in, const int* in_sizes, int n_in,
                              void* d_out, int out_size)
{
    const float* x  = (const float*)d_in[0];
    const float* w  = (const float*)d_in[1];
    const float* b  = (const float*)d_in[2];
    float* y = (float*)d_out;

    int N = in_sizes[0] / (CI * IN_H * IN_W);   // batch = 32
    dim3 grid((OUT_W + TILE_W - 1) / TILE_W,    // 4
              (OUT_H + TILE_H - 1) / TILE_H,    // 16
              N);                               // 32
    conv_mish_kernel<<<grid, 256>>>(x, w, b, y);
}

// round 2
// speedup vs baseline: 1.4829x; 1.4829x over previous
#include <cuda_runtime.h>
#include <math.h>

#define CI 16
#define CO 16
#define IN_H 256
#define IN_W 256
#define OUT_H 254
#define OUT_W 254

// 256 threads: tx 0..15 (4 cols each), ty 0..7 (2 rows each), tz 0..1 (8 cout each)
#define TILE_W 64
#define TILE_H 16
#define SM_ROWS 18  // TILE_H + 2
#define SM_COLS 66  // TILE_W + 2
#define SM_STRIDE 68
#define CHUNK 2     // ci channels resident in smem

typedef unsigned long long u64;

__device__ __forceinline__ void unpack2(u64 v, float& lo, float& hi) {
    asm("mov.b64 {%0,%1}, %2;" : "=f"(lo), "=f"(hi) : "l"(v));
}
// packed fp32x2 FMA: d = a*b + d  (SASS FFMA2 on sm_103a)
__device__ __forceinline__ void fma2(u64& d, u64 a, u64 b) {
    asm("fma.rn.f32x2 %0, %1, %2, %0;" : "+l"(d) : "l"(a), "l"(b));
}

// mish(v) = v * tanh(softplus(v)) = v * ((1+e^v)^2 - 1)/((1+e^v)^2 + 1)
__device__ __forceinline__ float mish_f(float v) {
    if (v > 30.0f) return v;
    float e  = __expf(v);
    float t  = 1.0f + e;
    float t2 = t * t;
    return v * __fdividef(t2 - 1.0f, t2 + 1.0f);
}

__global__ __launch_bounds__(256, 2)
void conv_mish_kernel(const float* __restrict__ x,
                      const float* __restrict__ w,
                      const float* __restrict__ bias,
                      float* __restrict__ y)
{
    // dual input arrays: sB is sA shifted left by one float -> all shifted
    // f32x2 window pairs are 8B-aligned loads (no register packing MOVs)
    __shared__ __align__(16) float sA[CHUNK * SM_ROWS * SM_STRIDE]; // 9792 B
    __shared__ __align__(16) float sB[CHUNK * SM_ROWS * SM_STRIDE]; // 9792 B
    __shared__ __align__(16) float wsm[CI * 9 * CO * 2];            // 18432 B (dup pairs)
    __shared__ float bsm[CO];

    const int tid    = threadIdx.x;
    const int tile_x = blockIdx.x * TILE_W;
    const int tile_y = blockIdx.y * TILE_H;
    const int n      = blockIdx.z;

    // weights as duplicated pairs: wsm_pair[(ci*9+k)*CO + co] = (w,w)
    for (int i = tid; i < CO * CI * 9; i += 256) {
        int co  = i / (CI * 9);
        int rem = i - co * (CI * 9);
        float wv = w[i];
        int p = (rem * CO + co) * 2;
        wsm[p] = wv; wsm[p + 1] = wv;
    }
    if (tid < CO) bsm[tid] = bias[tid];

    const int tx = tid & 15;
    const int ty = (tid >> 4) & 7;
    const int tz = tid >> 7;
    const int x0 = tx * 4;
    const int r0 = ty * 2;
    const int cobase = tz * 8;

    u64 acc[8][2][2];
    #pragma unroll
    for (int c = 0; c < 8; c++)
        #pragma unroll
        for (int r = 0; r < 2; r++)
            #pragma unroll
            for (int j = 0; j < 2; j++) acc[c][r][j] = 0ull;

    const float* xn = x + ((size_t)n * CI) * (IN_H * IN_W);

    for (int cc = 0; cc < CI / CHUNK; cc++) {
        if (cc) __syncthreads();
        // fill input chunk (coalesced); write both normal and shifted copies
        for (int i = tid; i < CHUNK * SM_ROWS * SM_COLS; i += 256) {
            int c  = i % SM_COLS;
            int t  = i / SM_COLS;
            int r  = t % SM_ROWS;
            int k  = t / SM_ROWS;
            int gy = tile_y + r;
            int gx = tile_x + c;
            float v = 0.0f;
            if (gy < IN_H && gx < IN_W)
                v = xn[((cc * CHUNK + k) * IN_H + gy) * IN_W + gx];
            int base = (k * SM_ROWS + r) * SM_STRIDE;
            sA[base + c] = v;
            if (c) sB[base + c - 1] = v;
        }
        __syncthreads();

        #pragma unroll
        for (int k2 = 0; k2 < CHUNK; k2++) {
            const int ci = cc * CHUNK + k2;
            #pragma unroll
            for (int ky = 0; ky < 3; ky++) {
                // input pairs for 2 output rows: P[r][s] = f32x2 window starting
                // at col x0+s.  even s -> sA, odd s -> sB; all aligned u64 loads.
                u64 P[2][5];
                #pragma unroll
                for (int r = 0; r < 2; r++) {
                    int base = (k2 * SM_ROWS + (r0 + ky + r)) * SM_STRIDE + x0;
                    const u64* pa = (const u64*)(sA + base);
                    const u64* pb = (const u64*)(sB + base);
                    ulonglong2 ta = *(const ulonglong2*)pa;
                    u64        a2 = pa[2];
                    ulonglong2 tb = *(const ulonglong2*)pb;
                    P[r][0] = ta.x; P[r][2] = ta.y; P[r][4] = a2;
                    P[r][1] = tb.x; P[r][3] = tb.y;
                }
                #pragma unroll
                for (int kx = 0; kx < 3; kx++) {
                    // 8 cout dup-pair weights for this (ci,ky,kx): broadcast loads
                    u64 wv[8];
                    const ulonglong2* wp = (const ulonglong2*)
                        ((const u64*)wsm + ((ci * 9 + ky * 3 + kx) * CO + cobase));
                    #pragma unroll
                    for (int c2 = 0; c2 < 4; c2++) {
                        ulonglong2 t = wp[c2];
                        wv[2 * c2]     = t.x;
                        wv[2 * c2 + 1] = t.y;
                    }
                    #pragma unroll
                    for (int c = 0; c < 8; c++)
                        #pragma unroll
                        for (int r = 0; r < 2; r++)
                            #pragma unroll
                            for (int j = 0; j < 2; j++)
                                fma2(acc[c][r][j], wv[c], P[r][kx + 2 * j]);
                }
            }
        }
    }

    // epilogue: +bias - 0.7, mish, float2 stores
    #pragma unroll
    for (int c = 0; c < 8; c++) {
        int co = cobase + c;
        float badd = bsm[co] - 0.7f;
        #pragma unroll
        for (int r = 0; r < 2; r++) {
            int oy = tile_y + r0 + r;
            if (oy >= OUT_H) continue;
            float* yrow = y + (((size_t)n * CO + co) * OUT_H + oy) * OUT_W;
            #pragma unroll
            for (int j = 0; j < 2; j++) {
                int ox = tile_x + x0 + 2 * j;
                if (ox < OUT_W) {
                    float lo, hi; unpack2(acc[c][r][j], lo, hi);
                    float2 o;
                    o.x = mish_f(lo + badd);
                    o.y = mish_f(hi + badd);
                    *(float2*)(yrow + ox) = o;
                }
            }
        }
    }
}

extern "C" void kernel_launch(void* const* d_in, const int* in_sizes, int n_in,
                              void* d_out, int out_size)
{
    const float* x  = (const float*)d_in[0];
    const float* w  = (const float*)d_in[1];
    const float* b  = (const float*)d_in[2];
    float* y = (float*)d_out;

    int N = in_sizes[0] / (CI * IN_H * IN_W);
    dim3 grid((OUT_W + TILE_W - 1) / TILE_W,    // 4
              (OUT_H + TILE_H - 1) / TILE_H,    // 16
              N);                               // 32
    conv_mish_kernel<<<grid, 256>>>(x, w, b, y);
}

// round 3
// speedup vs baseline: 1.8525x; 1.2492x over previous
#include <cuda_runtime.h>
#include <math.h>

#define CI 16
#define CO 16
#define IN_H 256
#define IN_W 256
#define OUT_H 254
#define OUT_W 254

// 256 threads: tx 0..15 (4 cols), ty 0..7 (2 rows), tz 0..1 (8 cout)
#define TILE_W 64
#define TILE_H 16
#define SM_ROWS 18      // TILE_H + 2
#define SM_STRIDE 68    // floats; 272 B row pitch (16B-aligned)
#define CHUNK_FLOATS (SM_ROWS * SM_STRIDE)

typedef unsigned long long u64;

__device__ __forceinline__ u64 pack2(float lo, float hi) {
    u64 r; asm("mov.b64 %0, {%1,%2};" : "=l"(r) : "f"(lo), "f"(hi)); return r;
}
__device__ __forceinline__ void unpack2(u64 v, float& lo, float& hi) {
    asm("mov.b64 {%0,%1}, %2;" : "=f"(lo), "=f"(hi) : "l"(v));
}
// packed fp32x2 FMA (SASS FFMA2): d = a*b + d
__device__ __forceinline__ void fma2(u64& d, u64 a, u64 b) {
    asm("fma.rn.f32x2 %0, %1, %2, %0;" : "+l"(d) : "l"(a), "l"(b));
}
__device__ __forceinline__ void cpasync16(unsigned dst, const void* src) {
    asm volatile("cp.async.cg.shared.global [%0], [%1], 16;" :: "r"(dst), "l"(src));
}
__device__ __forceinline__ void cpasync8(unsigned dst, const void* src) {
    asm volatile("cp.async.ca.shared.global [%0], [%1], 8;" :: "r"(dst), "l"(src));
}

// mish(v) = v * tanh(softplus(v)) = v * ((1+e^v)^2 - 1)/((1+e^v)^2 + 1)
__device__ __forceinline__ float mish_f(float v) {
    if (v > 30.0f) return v;
    float e  = __expf(v);
    float t  = 1.0f + e;
    float t2 = t * t;
    return v * __fdividef(t2 - 1.0f, t2 + 1.0f);
}

// async-copy one input channel tile (18 rows x 66 cols, halo) into smem stage.
// OOB rows/cols are redirected to valid dummy addresses; those values are never
// consumed (outputs needing them are guarded off in the epilogue).
__device__ __forceinline__ void load_chunk(unsigned sbase, const float* __restrict__ xc,
                                           int tile_x, int tile_y, int tid) {
    #pragma unroll
    for (int i = tid; i < SM_ROWS * 17; i += 256) {
        int r   = i / 17;
        int seg = i - r * 17;
        int gy = tile_y + r; if (gy > IN_H - 1) gy = IN_H - 1;   // dummy, unused
        int gx = tile_x + seg * 4;
        unsigned dst = sbase + (unsigned)(r * SM_STRIDE + seg * 4) * 4u;
        if (seg < 16) {
            cpasync16(dst, xc + (size_t)gy * IN_W + gx);
        } else {
            if (gx > IN_W - 2) gx = 0;                            // dummy, unused
            cpasync8(dst, xc + (size_t)gy * IN_W + gx);
        }
    }
}

__global__ __launch_bounds__(256, 2)
void conv_mish_kernel(const float* __restrict__ x,
                      const float* __restrict__ w,
                      const float* __restrict__ bias,
                      float* __restrict__ y)
{
    __shared__ __align__(16) float xin[2 * CHUNK_FLOATS];     // 9792 B (2 stages)
    __shared__ __align__(16) float wsm[CI * 9 * CO * 2];      // 18432 B (dup pairs)
    __shared__ float bsm[CO];

    const int tid    = threadIdx.x;
    const int tile_x = blockIdx.x * TILE_W;
    const int tile_y = blockIdx.y * TILE_H;
    const int n      = blockIdx.z;

    // weights as duplicated pairs: wsm_pair[(ci*9+k)*CO + co] = (w,w)
    for (int i = tid; i < CO * CI * 9; i += 256) {
        int co  = i / (CI * 9);
        int rem = i - co * (CI * 9);
        float wv = w[i];
        int p = (rem * CO + co) * 2;
        wsm[p] = wv; wsm[p + 1] = wv;
    }
    if (tid < CO) bsm[tid] = bias[tid];

    const int tx = tid & 15;
    const int ty = (tid >> 4) & 7;
    const int tz = tid >> 7;
    const int x0 = tx * 4;
    const int r0 = ty * 2;
    const int cobase = tz * 8;

    u64 acc[8][2][2];
    #pragma unroll
    for (int c = 0; c < 8; c++)
        #pragma unroll
        for (int r = 0; r < 2; r++)
            #pragma unroll
            for (int j = 0; j < 2; j++) acc[c][r][j] = 0ull;

    const float* xn = x + ((size_t)n * CI) * (IN_H * IN_W);
    unsigned sbase = (unsigned)__cvta_generic_to_shared(xin);

    // prologue: stage 0 in flight
    load_chunk(sbase, xn, tile_x, tile_y, tid);
    asm volatile("cp.async.commit_group;");

    #pragma unroll 2
    for (int cc = 0; cc < CI; cc++) {
        if (cc < CI - 1) {
            load_chunk(sbase + ((cc + 1) & 1) * (CHUNK_FLOATS * 4u),
                       xn + (size_t)(cc + 1) * (IN_H * IN_W), tile_x, tile_y, tid);
            asm volatile("cp.async.commit_group;");
            asm volatile("cp.async.wait_group 1;");
        } else {
            asm volatile("cp.async.wait_group 0;");
        }
        __syncthreads();   // chunk cc visible to all threads

        const float* xb = xin + (cc & 1) * CHUNK_FLOATS;
        const int ci = cc;

        #pragma unroll
        for (int ky = 0; ky < 3; ky++) {
            u64 P[2][5];
            #pragma unroll
            for (int r = 0; r < 2; r++) {
                const float* ip = xb + (r0 + ky + r) * SM_STRIDE + x0;
                float4 a  = *(const float4*)ip;
                float2 b2 = *(const float2*)(ip + 4);
                P[r][0] = pack2(a.x, a.y);
                P[r][1] = pack2(a.y, a.z);
                P[r][2] = pack2(a.z, a.w);
                P[r][3] = pack2(a.w, b2.x);
                P[r][4] = pack2(b2.x, b2.y);
            }
            #pragma unroll
            for (int kx = 0; kx < 3; kx++) {
                u64 wv[8];
                const ulonglong2* wp = (const ulonglong2*)
                    ((const u64*)wsm + ((ci * 9 + ky * 3 + kx) * CO + cobase));
                #pragma unroll
                for (int c2 = 0; c2 < 4; c2++) {
                    ulonglong2 t = wp[c2];
                    wv[2 * c2]     = t.x;
                    wv[2 * c2 + 1] = t.y;
                }
                #pragma unroll
                for (int c = 0; c < 8; c++)
                    #pragma unroll
                    for (int r = 0; r < 2; r++)
                        #pragma unroll
                        for (int j = 0; j < 2; j++)
                            fma2(acc[c][r][j], wv[c], P[r][kx + 2 * j]);
            }
        }
        __syncthreads();   // all done with stage (cc&1) before it is refilled
    }

    // epilogue: +bias - 0.7, mish, float2 stores
    #pragma unroll
    for (int c = 0; c < 8; c++) {
        int co = cobase + c;
        float badd = bsm[co] - 0.7f;
        #pragma unroll
        for (int r = 0; r < 2; r++) {
            int oy = tile_y + r0 + r;
            if (oy >= OUT_H) continue;
            float* yrow = y + (((size_t)n * CO + co) * OUT_H + oy) * OUT_W;
            #pragma unroll
            for (int j = 0; j < 2; j++) {
                int ox = tile_x + x0 + 2 * j;
                if (ox < OUT_W) {
                    float lo, hi; unpack2(acc[c][r][j], lo, hi);
                    float2 o;
                    o.x = mish_f(lo + badd);
                    o.y = mish_f(hi + badd);
                    *(float2*)(yrow + ox) = o;
                }
            }
        }
    }
}

extern "C" void kernel_launch(void* const* d_in, const int* in_sizes, int n_in,
                              void* d_out, int out_size)
{
    const float* x  = (const float*)d_in[0];
    const float* w  = (const float*)d_in[1];
    const float* b  = (const float*)d_in[2];
    float* y = (float*)d_out;

    int N = in_sizes[0] / (CI * IN_H * IN_W);
    dim3 grid((OUT_W + TILE_W - 1) / TILE_W,    // 4
              (OUT_H + TILE_H - 1) / TILE_H,    // 16
              N);                               // 32
    conv_mish_kernel<<<grid, 256>>>(x, w, b, y);
}

// round 5
// speedup vs baseline: 3.7755x; 2.0381x over previous
#include <cuda_runtime.h>
#include <stdint.h>

#define IN_W 256
#define IN_HW 65536
#define OUT_W 254

#define R_OUT 8            // output rows per CTA
#define ROWS_IN 10         // R_OUT + 2
#define POS 130            // 128 + 2 halo input positions
#define ROW_W 2080         // POS * 16 words per input row
#define A_WORDS (ROWS_IN * ROW_W)        // 20800
#define BF_WORDS 2304                    // 3 ky * 6 ks * 2 h * 32 lanes * 2 regs
#define SMEM_BYTES ((A_WORDS + BF_WORDS + 16) * 4)   // 92,544 B

// word-index swizzle: XOR bits[5:7) into bits[2:4) -> conflict-free fragments & stores
__device__ __forceinline__ uint32_t swzw(uint32_t w) {
    return w ^ (((w >> 5) & 3u) << 2);
}
__device__ __forceinline__ uint32_t tf32r(float f) {
    uint32_t r; asm("cvt.rna.tf32.f32 %0, %1;" : "=r"(r) : "f"(f)); return r;
}
__device__ __forceinline__ void mma_tf32(float c[4], uint32_t a0, uint32_t a1,
                                         uint32_t a2, uint32_t a3,
                                         uint32_t b0, uint32_t b1) {
    asm("mma.sync.aligned.m16n8k8.row.col.f32.tf32.tf32.f32 "
        "{%0,%1,%2,%3}, {%4,%5,%6,%7}, {%8,%9}, {%0,%1,%2,%3};"
        : "+f"(c[0]), "+f"(c[1]), "+f"(c[2]), "+f"(c[3])
        : "r"(a0), "r"(a1), "r"(a2), "r"(a3), "r"(b0), "r"(b1));
}
__device__ __forceinline__ float mish_f(float v) {
    if (v > 30.0f) return v;
    float e  = __expf(v);
    float t  = 1.0f + e;
    float t2 = t * t;
    return v * __fdividef(t2 - 1.0f, t2 + 1.0f);
}

__global__ __launch_bounds__(256, 2)
void conv_tc_kernel(const float* __restrict__ x,
                    const float* __restrict__ w,
                    const float* __restrict__ bias,
                    float* __restrict__ y)
{
    extern __shared__ uint32_t sm[];
    uint32_t* Asm = sm;                     // [row][pos][ci16], swizzled, tf32 bits
    uint32_t* Bf  = sm + A_WORDS;           // lane-ordered B fragments
    float*    bsm = (float*)(sm + A_WORDS + BF_WORDS);

    const int tid  = threadIdx.x;
    const int wid  = tid >> 5;
    const int lane = tid & 31;
    const int lm   = lane >> 2;   // groupID
    const int lk   = lane & 3;    // threadID_in_group
    const int X0   = blockIdx.x * 128;
    const int Y0   = blockIdx.y * R_OUT;
    const int n    = blockIdx.z;

    if (tid < 16) bsm[tid] = bias[tid];

    // ---- B fragments: Bf[(ky*6+ks)*128 + h*64 + lane*2 + reg]
    for (int i = tid; i < BF_WORDS; i += 256) {
        int reg = i & 1;
        int ln  = (i >> 1) & 31;
        int h   = (i >> 6) & 1;
        int t   = i >> 7;              // ky*6+ks
        int ks  = t % 6, ky = t / 6;
        int k   = ks * 8 + (ln & 3) + reg * 4;   // 0..47
        int co  = h * 8 + (ln >> 2);
        int kx  = k >> 4, ci = k & 15;
        Bf[i] = tf32r(w[(co * 16 + ci) * 9 + ky * 3 + kx]);
    }

    // ---- input tile transpose: gmem NCHW -> smem [row][pos][ci], tf32, swizzled
    const float* xn = x + (size_t)n * 16 * IN_HW;
    for (int i = tid; i < ROWS_IN * POS; i += 256) {
        int pos = i % POS;
        int row = i / POS;
        int gy = Y0 + row; if (gy > 255) gy = 255;   // clamped rows feed only guarded outputs
        int gx = X0 + pos; if (gx > 255) gx = 255;
        const float* src = xn + gy * IN_W + gx;
        uint32_t wb = row * ROW_W + pos * 16;
        #pragma unroll
        for (int c4 = 0; c4 < 4; c4++) {
            uint4 q;
            q.x = tf32r(src[(c4 * 4 + 0) * IN_HW]);
            q.y = tf32r(src[(c4 * 4 + 1) * IN_HW]);
            q.z = tf32r(src[(c4 * 4 + 2) * IN_HW]);
            q.w = tf32r(src[(c4 * 4 + 3) * IN_HW]);
            *(uint4*)(Asm + swzw(wb + c4 * 4)) = q;
        }
    }
    __syncthreads();

    // ---- mainloop: warp wid computes output row Y0+wid, 8 tiles of 16 x-positions
    const int r  = wid;
    const int yo = Y0 + r;

    #pragma unroll 1
    for (int t = 0; t < 8; t++) {
        const int posbase = t * 16;
        float c0[4] = {0.f, 0.f, 0.f, 0.f};
        float c1[4] = {0.f, 0.f, 0.f, 0.f};

        #pragma unroll
        for (int ky = 0; ky < 3; ky++) {
            uint32_t rb = (uint32_t)((r + ky) * ROW_W + (posbase + lm) * 16 + lk);
            const uint32_t* bp = Bf + ky * 6 * 128 + lane * 2;
            #pragma unroll
            for (int ks = 0; ks < 6; ks++) {
                uint32_t sw  = swzw(rb + ks * 8);
                uint32_t sw4 = sw ^ 4u;
                uint32_t a0 = Asm[sw];
                uint32_t a1 = Asm[sw + 128];
                uint32_t a2 = Asm[sw4];
                uint32_t a3 = Asm[sw4 + 128];
                uint2 b0 = *(const uint2*)(bp + ks * 128);
                uint2 b1 = *(const uint2*)(bp + ks * 128 + 64);
                mma_tf32(c0, a0, a1, a2, a3, b0.x, b0.y);
                mma_tf32(c1, a0, a1, a2, a3, b1.x, b1.y);
            }
        }

        // epilogue: c[e] -> (m = lm + (e>=2)*8, co = h*8 + lk*2 + (e&1))
        if (yo < OUT_W) {
            int xoA = X0 + posbase + lm;
            int xoB = xoA + 8;
            float* yn = y + ((size_t)n * 16) * (OUT_W * OUT_W) + (size_t)yo * OUT_W;
            #pragma unroll
            for (int h = 0; h < 2; h++) {
                const float* cc = h ? c1 : c0;
                int coA = h * 8 + lk * 2;
                float bA = bsm[coA]     - 0.7f;
                float bB = bsm[coA + 1] - 0.7f;
                if (xoA < OUT_W) {
                    yn[(size_t)coA       * (OUT_W * OUT_W) + xoA] = mish_f(cc[0] + bA);
                    yn[(size_t)(coA + 1) * (OUT_W * OUT_W) + xoA] = mish_f(cc[1] + bB);
                }
                if (xoB < OUT_W) {
                    yn[(size_t)coA       * (OUT_W * OUT_W) + xoB] = mish_f(cc[2] + bA);
                    yn[(size_t)(coA + 1) * (OUT_W * OUT_W) + xoB] = mish_f(cc[3] + bB);
                }
            }
        }
    }
}

extern "C" void kernel_launch(void* const* d_in, const int* in_sizes, int n_in,
                              void* d_out, int out_size)
{
    const float* x  = (const float*)d_in[0];
    const float* w  = (const float*)d_in[1];
    const float* b  = (const float*)d_in[2];
    float* y = (float*)d_out;

    cudaFuncSetAttribute(conv_tc_kernel,
                         cudaFuncAttributeMaxDynamicSharedMemorySize, SMEM_BYTES);

    int N = in_sizes[0] / (16 * IN_HW);                 // 32
    dim3 grid(2, (OUT_W + R_OUT - 1) / R_OUT, N);       // 2 x 32 x 32
    conv_tc_kernel<<<grid, 256, SMEM_BYTES>>>(x, w, b, y);
}